// round 6
// baseline (speedup 1.0000x reference)
#include <cuda_runtime.h>

#define N 8192
#define NITER 20
#define TOLF 1e-10f
#define TDIM 128                        // tile edge
#define NTB (N / TDIM)                  // 64
#define NTILES (NTB * (NTB + 1) / 2)    // 2080
#define GRID 592                        // 148 SMs * 4 — exact fill
#define TPB 256
#define OWNERS 512                      // blocks owning vector slices
#define ROWS_PB 16
#define PAP_PAD 2304                    // 9 * 256, zero-padded
#define RES_T 1728                      // first 108 MB of tiles: default L2 policy
#define NSYNC (2 * NITER + 1)
#define NV4 (N / 4)

// Persistent device state (no allocations allowed)
__device__ float g_r[N];
__device__ float g_pbuf[2][N];              // double-buffered p
__device__ float g_ypart[NTB][NTB][TDIM];   // 2 MB of per-tile y partials
__device__ float g_pap[PAP_PAD];            // per-tile pAp contributions
__device__ float g_rr[OWNERS];
__device__ unsigned g_sync[NSYNC];
__device__ unsigned g_ticket[NITER];

__device__ __forceinline__ float warp_red(float v) {
#pragma unroll
    for (int o = 16; o; o >>= 1) v += __shfl_xor_sync(0xffffffffu, v, o);
    return v;
}

// Software grid barrier; all 592 blocks co-resident (4/SM * 148 SMs).
__device__ __forceinline__ void gsync(int idx) {
    __syncthreads();
    if (threadIdx.x == 0) {
        __threadfence();
        unsigned arr = atomicAdd(&g_sync[idx], 1u);
        if (arr + 1u < (unsigned)GRID) {
            volatile unsigned* c = &g_sync[idx];
            while (*c < (unsigned)GRID) { }
        }
        __threadfence();
    }
    __syncthreads();
}

// Deterministic fixed-order reduce of per-tile pAp partials (identical everywhere).
__device__ __forceinline__ float reduce_pap(float* sred) {
    int tid = threadIdx.x;
    float s = 0.f;
#pragma unroll
    for (int k = 0; k < PAP_PAD / TPB; k++)
        s += __ldcg(g_pap + tid + k * TPB);
    s = warp_red(s);
    if ((tid & 31) == 0) sred[tid >> 5] = s;
    __syncthreads();
    float tot = 0.f;
#pragma unroll
    for (int w = 0; w < TPB / 32; w++) tot += sred[w];
    __syncthreads();
    return tot;
}

__device__ __forceinline__ float reduce_rr(float* sred) {
    int tid = threadIdx.x;
    float s = 0.f;
#pragma unroll
    for (int k = 0; k < OWNERS / TPB; k++)
        s += __ldcg(g_rr + tid + k * TPB);
    s = warp_red(s);
    if ((tid & 31) == 0) sred[tid >> 5] = s;
    __syncthreads();
    float tot = 0.f;
#pragma unroll
    for (int w = 0; w < TPB / 32; w++) tot += sred[w];
    __syncthreads();
    return tot;
}

__global__ void k_reset() {
    int t = threadIdx.x;
    for (int i = t; i < NSYNC; i += 256) g_sync[i] = 0u;
    for (int i = t; i < NITER; i += 256) g_ticket[i] = 0u;
    for (int i = NTILES + t; i < PAP_PAD; i += 256) g_pap[i] = 0.f;
}

__global__ void __launch_bounds__(TPB, 4) k_cg(const float* __restrict__ M,
                                               const float* __restrict__ RHS,
                                               float* __restrict__ out) {
    const int tid  = threadIdx.x;
    const int b    = blockIdx.x;
    const int w    = tid >> 5;
    const int lane = tid & 31;
    const bool owner = (b < OWNERS);

    __shared__ __align__(16) float sp_i[TDIM];
    __shared__ __align__(16) float sp_j[TDIM];
    __shared__ float srow[TDIM][33];                 // per-lane row-dot partials
    __shared__ __align__(16) float scol[8][TDIM];    // per-warp column partials
    __shared__ float sred[TPB / 32];
    __shared__ float sX[ROWS_PB], sR[ROWS_PB], sP[ROWS_PB], sAp[ROWS_PB];
    __shared__ unsigned s_t;

    // ---- init
    if (owner && tid < ROWS_PB) {
        int i = b * ROWS_PB + tid;
        float v = RHS[i];
        g_r[i] = v;
        g_pbuf[0][i] = v;      // p for iter 0
        g_pbuf[1][i] = 0.f;    // avoid NaN in iter-0 on-the-fly fma
        sR[tid] = v; sP[tid] = v; sX[tid] = 0.f;
    }
    __syncthreads();
    if (owner && tid == 0) {
        float rs = 0.f;
#pragma unroll
        for (int k = 0; k < ROWS_PB; k++) rs += sR[k] * sR[k];
        g_rr[b] = rs;
    }
    int sidx = 0;
    gsync(sidx++);
    float rtr  = reduce_rr(sred);
    float beta = 0.f;

    const float4* __restrict__ M4 = reinterpret_cast<const float4*>(M);

    for (int it = 0; it < NITER; it++) {
        if (!(rtr > TOLF)) break;                 // bitwise-uniform across blocks

        const float* __restrict__ pprev = g_pbuf[(it + 1) & 1];
        float* __restrict__ pcur        = g_pbuf[it & 1];

        // first ticket; owners update local p and publish for NEXT iteration's tiles
        if (tid == 0) s_t = atomicAdd(&g_ticket[it], 1u);
        if (owner && tid < ROWS_PB) {
            float pn = fmaf(beta, sP[tid], sR[tid]);   // same fma as tiles do
            sP[tid] = pn;
            pcur[b * ROWS_PB + tid] = pn;
        }
        __syncthreads();
        unsigned t = s_t;

        // ================= Phase 1: dynamically scheduled tile products ==========
        while (t < NTILES) {
            int ti = 0, rem = (int)t;
            while (rem >= NTB - ti) { rem -= NTB - ti; ti++; }
            const int tj = ti + rem;
            const bool diag = (ti == tj);

            // p slices on the fly: bitwise identical in every block
            if (tid < TDIM) {
                sp_i[tid] = fmaf(beta, __ldcg(pprev + ti * TDIM + tid),
                                        __ldcg(g_r   + ti * TDIM + tid));
            } else {
                int e = tid - TDIM;
                sp_j[e] = fmaf(beta, __ldcg(pprev + tj * TDIM + e),
                                      __ldcg(g_r   + tj * TDIM + e));
            }
            __syncthreads();

            const float4* spj4 = reinterpret_cast<const float4*>(sp_j);
            const float4 v = spj4[lane];
            float4 acc = {0.f, 0.f, 0.f, 0.f};
            const size_t base = ((size_t)ti * TDIM + w * 16) * NV4
                              + (size_t)tj * (TDIM / 4) + lane;

            if (t < RES_T) {
#pragma unroll 4
                for (int r = 0; r < 16; r++) {
                    float4 m = __ldg(M4 + base + (size_t)r * NV4);
                    float s = m.x * v.x;
                    s = fmaf(m.y, v.y, s); s = fmaf(m.z, v.z, s); s = fmaf(m.w, v.w, s);
                    srow[w * 16 + r][lane] = s;
                    float pi = sp_i[w * 16 + r];
                    acc.x = fmaf(m.x, pi, acc.x); acc.y = fmaf(m.y, pi, acc.y);
                    acc.z = fmaf(m.z, pi, acc.z); acc.w = fmaf(m.w, pi, acc.w);
                }
            } else {
#pragma unroll 4
                for (int r = 0; r < 16; r++) {
                    float4 m = __ldcs(M4 + base + (size_t)r * NV4);
                    float s = m.x * v.x;
                    s = fmaf(m.y, v.y, s); s = fmaf(m.z, v.z, s); s = fmaf(m.w, v.w, s);
                    srow[w * 16 + r][lane] = s;
                    float pi = sp_i[w * 16 + r];
                    acc.x = fmaf(m.x, pi, acc.x); acc.y = fmaf(m.y, pi, acc.y);
                    acc.z = fmaf(m.z, pi, acc.z); acc.w = fmaf(m.w, pi, acc.w);
                }
            }
            reinterpret_cast<float4*>(scol[w])[lane] = acc;
            if (tid == 0) s_t = atomicAdd(&g_ticket[it], 1u);   // overlap next grab
            __syncthreads();

            // deferred reductions (threads 0..127), per-tile deterministic results
            if (tid < TDIM) {
                float yr = 0.f;
#pragma unroll
                for (int k = 0; k < 32; k++) yr += srow[tid][k];
                g_ypart[ti][tj][tid] = yr;
                float papc = yr * sp_i[tid];
                if (!diag) {
                    float yc = 0.f;
#pragma unroll
                    for (int ww = 0; ww < 8; ww++) yc += scol[ww][tid];
                    g_ypart[tj][ti][tid] = yc;
                    papc = fmaf(yc, sp_j[tid], papc);
                }
                papc = warp_red(papc);
                if (lane == 0) sred[tid >> 5] = papc;
            }
            __syncthreads();
            if (tid == 0)
                g_pap[t] = sred[0] + sred[1] + sred[2] + sred[3];
            unsigned tn = s_t;
            __syncthreads();        // protect sp/srow rewrite next round
            t = tn;
        }
        gsync(sidx++);

        // ================= Phase 2: alpha; owners assemble Ap, update X/r ========
        float pAp   = reduce_pap(sred);
        float alpha = rtr / pAp;

        if (owner) {
            int R  = b >> 3;                    // 128-row block
            int e  = (b & 7) * ROWS_PB + 2 * w; // this warp's two rows
            float s0 = __ldcg(&g_ypart[R][lane][e])     + __ldcg(&g_ypart[R][lane + 32][e]);
            float s1 = __ldcg(&g_ypart[R][lane][e + 1]) + __ldcg(&g_ypart[R][lane + 32][e + 1]);
            s0 = warp_red(s0);
            s1 = warp_red(s1);
            if (lane == 0) { sAp[2 * w] = s0; sAp[2 * w + 1] = s1; }
        }
        __syncthreads();
        if (owner && tid < ROWS_PB) {
            sX[tid]  = fmaf(alpha, sP[tid], sX[tid]);
            float rn = fmaf(-alpha, sAp[tid], sR[tid]);
            sR[tid]  = rn;
            g_r[b * ROWS_PB + tid] = rn;
        }
        __syncthreads();
        if (owner && tid == 0) {
            float rs = 0.f;
#pragma unroll
            for (int k = 0; k < ROWS_PB; k++) rs += sR[k] * sR[k];
            g_rr[b] = rs;
        }
        gsync(sidx++);

        // ================= Phase 3 (no extra sync): beta =========================
        float rrn = reduce_rr(sred);
        beta = rrn / rtr;
        rtr  = rrn;
    }

    if (owner && tid < ROWS_PB) out[b * ROWS_PB + tid] = sX[tid];
}

extern "C" void kernel_launch(void* const* d_in, const int* in_sizes, int n_in,
                              void* d_out, int out_size) {
    // metadata order: X (shape only), M, RHS
    const float* M   = (const float*)d_in[1];
    const float* RHS = (const float*)d_in[2];
    float* out = (float*)d_out;

    k_reset<<<1, 256>>>();
    k_cg<<<GRID, TPB>>>(M, RHS, out);
}

// round 7
// speedup vs baseline: 1.1062x; 1.1062x over previous
#include <cuda_runtime.h>

#define N 8192
#define NITER 20
#define TOLF 1e-10f
#define TDIM 128
#define NTB (N / TDIM)                  // 64
#define NTILES (NTB * (NTB + 1) / 2)    // 2080
#define GRID 444                        // 148 SMs * 3 — exact fill at occ 3
#define TPB 256
#define OWNERS 256
#define ROWS_PB 32
#define PAP_PAD 2304                    // 9 * 256
#define NSYNC (2 * NITER + 1)
#define NV4 (N / 4)

// Persistent device state (no allocations allowed)
__device__ __align__(16) float g_r[N];
__device__ __align__(16) float g_pprev[N];
__device__ float g_ypart[NTB][NTB][TDIM];   // [row-block][contrib][elem], 2 MB
__device__ float g_pap[PAP_PAD];
__device__ float g_rr[OWNERS];
__device__ unsigned g_sync[NSYNC];
__device__ unsigned g_ticket[NITER];
__device__ int g_tij[NTILES];

__device__ __forceinline__ float warp_red(float v) {
#pragma unroll
    for (int o = 16; o; o >>= 1) v += __shfl_xor_sync(0xffffffffu, v, o);
    return v;
}

// Software grid barrier; all 444 blocks co-resident (3/SM * 148).
__device__ __forceinline__ void gsync(int idx) {
    __syncthreads();
    if (threadIdx.x == 0) {
        __threadfence();
        unsigned arr = atomicAdd(&g_sync[idx], 1u);
        if (arr + 1u < (unsigned)GRID) {
            volatile unsigned* c = &g_sync[idx];
            while (*c < (unsigned)GRID) { }
        }
        __threadfence();
    }
    __syncthreads();
}

__device__ __forceinline__ float reduce_pap(float* sred) {
    int tid = threadIdx.x;
    float s = 0.f;
#pragma unroll
    for (int k = 0; k < PAP_PAD / TPB; k++)
        s += __ldcg(g_pap + tid + k * TPB);
    s = warp_red(s);
    if ((tid & 31) == 0) sred[tid >> 5] = s;
    __syncthreads();
    float tot = 0.f;
#pragma unroll
    for (int w = 0; w < TPB / 32; w++) tot += sred[w];
    __syncthreads();
    return tot;
}

__device__ __forceinline__ float reduce_rr(float* sred) {
    int tid = threadIdx.x;
    float s = warp_red(__ldcg(g_rr + tid));   // OWNERS == TPB
    if ((tid & 31) == 0) sred[tid >> 5] = s;
    __syncthreads();
    float tot = 0.f;
#pragma unroll
    for (int w = 0; w < TPB / 32; w++) tot += sred[w];
    __syncthreads();
    return tot;
}

__global__ void k_reset() {
    int t0 = threadIdx.x;
    for (int i = t0; i < NSYNC; i += 256) g_sync[i] = 0u;
    for (int i = t0; i < NITER; i += 256) g_ticket[i] = 0u;
    for (int i = NTILES + t0; i < PAP_PAD; i += 256) g_pap[i] = 0.f;
    for (int t = t0; t < NTILES; t += 256) {
        int ti = 0, rem = t;
        while (rem >= NTB - ti) { rem -= NTB - ti; ti++; }
        g_tij[t] = (ti << 8) | (ti + rem);
    }
}

__global__ void __launch_bounds__(TPB, 3) k_cg(const float* __restrict__ M,
                                               const float* __restrict__ RHS,
                                               float* __restrict__ out) {
    const int tid  = threadIdx.x;
    const int b    = blockIdx.x;
    const int w    = tid >> 5;
    const int lane = tid & 31;
    const bool owner = (b < OWNERS);

    __shared__ __align__(16) float sp[N];          // full p vector (32 KB)
    __shared__ __align__(16) float scol[8][TDIM];  // per-warp column partials (4 KB)
    __shared__ float sred[TPB / 32];
    __shared__ float sredp[12];
    __shared__ float sAp[ROWS_PB], sX[ROWS_PB], sR[ROWS_PB];
    __shared__ unsigned s_t;

    // ---- init
    if (owner && tid < ROWS_PB) {
        int i = b * ROWS_PB + tid;
        float v = RHS[i];
        g_r[i] = v;
        g_pprev[i] = 0.f;     // beta0 = 0 -> sp = RHS
        sR[tid] = v;
        sX[tid] = 0.f;
    }
    __syncthreads();
    if (owner && tid == 0) {
        float rs = 0.f;
#pragma unroll
        for (int k = 0; k < ROWS_PB; k++) rs += sR[k] * sR[k];
        g_rr[b] = rs;
    }
    int sidx = 0;
    gsync(sidx++);
    float rtr  = reduce_rr(sred);
    float beta = 0.f;

    const float4* __restrict__ M4 = reinterpret_cast<const float4*>(M);

    for (int it = 0; it < NITER; it++) {
        if (!(rtr > TOLF)) break;                 // bitwise-uniform across blocks

        // ---- stage p = r + beta * pprev (bitwise identical in every block)
        {
            const float4* r4  = reinterpret_cast<const float4*>(g_r);
            const float4* pp4 = reinterpret_cast<const float4*>(g_pprev);
            float4* sp4 = reinterpret_cast<float4*>(sp);
#pragma unroll
            for (int k = 0; k < (N / 4) / TPB; k++) {
                int idx = tid + k * TPB;
                float4 a = __ldcg(pp4 + idx);
                float4 c = __ldcg(r4 + idx);
                sp4[idx] = make_float4(fmaf(beta, a.x, c.x), fmaf(beta, a.y, c.y),
                                       fmaf(beta, a.z, c.z), fmaf(beta, a.w, c.w));
            }
        }
        if (tid == 0) s_t = atomicAdd(&g_ticket[it], 1u);
        __syncthreads();
        unsigned t = s_t;

        // ================= Phase 1: work-stealing tile loop =================
        while (t < NTILES) {
            const int ij = __ldg(&g_tij[t]);
            const int ti = ij >> 8, tj = ij & 255;
            const bool diag = (ti == tj);

            const float4 v = reinterpret_cast<const float4*>(sp + tj * TDIM)[lane];
            const float* spi = sp + ti * TDIM + w * 16;
            const size_t base = (size_t)(ti * TDIM + w * 16) * NV4
                              + (size_t)tj * (TDIM / 4) + lane;

            float rp[16];
            float4 ca = {0.f, 0.f, 0.f, 0.f};
#pragma unroll
            for (int r = 0; r < 16; r++) {
                float4 m = __ldcs(M4 + base + (size_t)r * NV4);
                float s = m.x * v.x;
                s = fmaf(m.y, v.y, s); s = fmaf(m.z, v.z, s); s = fmaf(m.w, v.w, s);
                rp[r] = s;
                if (!diag) {
                    float pi = spi[r];
                    ca.x = fmaf(m.x, pi, ca.x); ca.y = fmaf(m.y, pi, ca.y);
                    ca.z = fmaf(m.z, pi, ca.z); ca.w = fmaf(m.w, pi, ca.w);
                }
            }
            // register-resident row reductions (no smem pass)
            float papr = 0.f;
#pragma unroll
            for (int r = 0; r < 16; r++) {
                float yr = warp_red(rp[r]);
                if (lane == 0) {
                    g_ypart[ti][tj][w * 16 + r] = yr;
                    papr = fmaf(yr, spi[r], papr);
                }
            }
            if (!diag) reinterpret_cast<float4*>(scol[w])[lane] = ca;
            if (lane == 0) sredp[w] = papr;
            if (tid == 0) s_t = atomicAdd(&g_ticket[it], 1u);   // overlap
            __syncthreads();

            if (tid < TDIM) {
                float papc = 0.f;
                if (!diag) {
                    float yc = 0.f;
#pragma unroll
                    for (int ww = 0; ww < 8; ww++) yc += scol[ww][tid];
                    g_ypart[tj][ti][tid] = yc;
                    papc = yc * sp[tj * TDIM + tid];
                }
                papc = warp_red(papc);
                if ((tid & 31) == 0) sredp[8 + (tid >> 5)] = papc;
            }
            __syncthreads();
            if (tid == 0) {
                float s = 0.f;
#pragma unroll
                for (int k = 0; k < 12; k++) s += sredp[k];
                g_pap[t] = s;
            }
            unsigned tn = s_t;
            __syncthreads();         // protect scol/sredp before next tile
            t = tn;
        }
        gsync(sidx++);

        // ================= Phase 2: alpha; owners assemble Ap, update X/r ====
        float pAp   = reduce_pap(sred);
        float alpha = rtr / pAp;

        if (owner) {
#pragma unroll
            for (int q = 0; q < 4; q++) {
                int i = b * ROWS_PB + w * 4 + q;
                int R = i >> 7, e = i & 127;
                float s0 = __ldcg(&g_ypart[R][lane][e])
                         + __ldcg(&g_ypart[R][lane + 32][e]);
                s0 = warp_red(s0);
                if (lane == 0) sAp[w * 4 + q] = s0;
            }
        }
        __syncthreads();
        if (owner && tid < ROWS_PB) {
            int i = b * ROWS_PB + tid;
            float pi_ = sp[i];
            sX[tid] = fmaf(alpha, pi_, sX[tid]);
            float rn = fmaf(-alpha, sAp[tid], sR[tid]);
            sR[tid] = rn;
            g_r[i] = rn;
            g_pprev[i] = pi_;       // current p -> prev for next iteration
        }
        __syncthreads();
        if (owner && tid == 0) {
            float rs = 0.f;
#pragma unroll
            for (int k = 0; k < ROWS_PB; k++) rs += sR[k] * sR[k];
            g_rr[b] = rs;
        }
        gsync(sidx++);

        float rrn = reduce_rr(sred);
        beta = rrn / rtr;
        rtr  = rrn;
    }

    if (owner && tid < ROWS_PB) out[b * ROWS_PB + tid] = sX[tid];
}

extern "C" void kernel_launch(void* const* d_in, const int* in_sizes, int n_in,
                              void* d_out, int out_size) {
    // metadata order: X (shape only), M, RHS
    const float* M   = (const float*)d_in[1];
    const float* RHS = (const float*)d_in[2];
    float* out = (float*)d_out;

    k_reset<<<1, 256>>>();
    k_cg<<<GRID, TPB>>>(M, RHS, out);
}